// round 16
// baseline (speedup 1.0000x reference)
#include <cuda_runtime.h>
#include <cuda_fp16.h>
#include <cstdint>

// Problem constants
#define BB 4
#define SS 8192
#define DD 512
#define HH 8
#define DHD 64
#define MR (BB*SS)          // 32768 rows
#define EPSF 1e-6f
#define KVC 32

// Output layout: out [B,S,D], k_v [B,H,DH,DH], z [B,H,DH]
#define OFF_KV ((size_t)MR*DD)
#define NKV (BB*HH*DHD*DHD)
#define OFF_Z (OFF_KV + NKV)
#define NZ (BB*HH*DHD)

// Scratch (device globals)
__device__ __half g_qh[(size_t)MR*DD];   // fp16 inputs
__device__ __half g_kh[(size_t)MR*DD];
__device__ __half g_vh[(size_t)MR*DD];
__device__ __half g_Wh4[(size_t)4*DD*DD]; // fp16 weights: Wq,Wk,Wv,Wo
__device__ __half g_Q[(size_t)MR*DD];    // fp16 projected
__device__ __half g_K[(size_t)MR*DD];
__device__ __half g_V[(size_t)MR*DD];
__device__ __half g_att[(size_t)MR*DD];  // fp16 attention output
__device__ float g_kv_part[(size_t)KVC*BB*HH*DHD*DHD];
__device__ float g_z_part[(size_t)KVC*BB*HH*DHD];
__device__ __half g_kvT[NKV];
__device__ float g_z[NZ];

// ---------------------------------------------------------------------------
__device__ __forceinline__ void mma16816(float* c, const uint32_t* a, const uint32_t* b) {
    asm volatile(
        "mma.sync.aligned.m16n8k16.row.col.f32.f16.f16.f32 "
        "{%0,%1,%2,%3}, {%4,%5,%6,%7}, {%8,%9}, {%0,%1,%2,%3};\n"
        : "+f"(c[0]), "+f"(c[1]), "+f"(c[2]), "+f"(c[3])
        : "r"(a[0]), "r"(a[1]), "r"(a[2]), "r"(a[3]), "r"(b[0]), "r"(b[1]));
}

__device__ __forceinline__ void ldsm4(uint32_t* r, uint32_t addr) {
    asm volatile("ldmatrix.sync.aligned.m8n8.x4.shared.b16 {%0,%1,%2,%3}, [%4];"
        : "=r"(r[0]), "=r"(r[1]), "=r"(r[2]), "=r"(r[3]) : "r"(addr));
}

__device__ __forceinline__ void ldsm4t(uint32_t* r, uint32_t addr) {
    asm volatile("ldmatrix.sync.aligned.m8n8.x4.trans.shared.b16 {%0,%1,%2,%3}, [%4];"
        : "=r"(r[0]), "=r"(r[1]), "=r"(r[2]), "=r"(r[3]) : "r"(addr));
}

__device__ __forceinline__ void cpasync16(uint32_t saddr, const void* gptr) {
    asm volatile("cp.async.cg.shared.global [%0], [%1], 16;" :: "r"(saddr), "l"(gptr) : "memory");
}
#define CP_COMMIT() asm volatile("cp.async.commit_group;" ::: "memory")
#define CP_WAIT2()  asm volatile("cp.async.wait_group 2;" ::: "memory")

// ===========================================================================
// Conversion kernels
// ===========================================================================
__global__ void __launch_bounds__(256)
cvt_inputs_kernel(const float* __restrict__ q, const float* __restrict__ k,
                  const float* __restrict__ v)
{
    const size_t N4 = (size_t)MR * DD / 4;
    const size_t stride = (size_t)gridDim.x * blockDim.x;
    for (size_t i = (size_t)blockIdx.x * blockDim.x + threadIdx.x; i < N4; i += stride) {
        float4 a = ((const float4*)q)[i];
        float4 b = ((const float4*)k)[i];
        float4 c = ((const float4*)v)[i];
        __half2 r0 = __floats2half2_rn(a.x, a.y), r1 = __floats2half2_rn(a.z, a.w);
        ((uint2*)g_qh)[i] = make_uint2(*(uint32_t*)&r0, *(uint32_t*)&r1);
        r0 = __floats2half2_rn(b.x, b.y); r1 = __floats2half2_rn(b.z, b.w);
        ((uint2*)g_kh)[i] = make_uint2(*(uint32_t*)&r0, *(uint32_t*)&r1);
        r0 = __floats2half2_rn(c.x, c.y); r1 = __floats2half2_rn(c.z, c.w);
        ((uint2*)g_vh)[i] = make_uint2(*(uint32_t*)&r0, *(uint32_t*)&r1);
    }
}

__global__ void __launch_bounds__(256)
cvt_weights_kernel(const float* __restrict__ Wq, const float* __restrict__ Wk,
                   const float* __restrict__ Wv, const float* __restrict__ Wo)
{
    const int NW = DD * DD / 4;
    const int i = blockIdx.x * blockDim.x + threadIdx.x;
    const float* srcs[4] = {Wq, Wk, Wv, Wo};
    if (i < NW) {
#pragma unroll
        for (int w = 0; w < 4; w++) {
            float4 a = ((const float4*)srcs[w])[i];
            __half2 r0 = __floats2half2_rn(a.x, a.y), r1 = __floats2half2_rn(a.z, a.w);
            ((uint2*)(g_Wh4 + (size_t)w * DD * DD))[i] = make_uint2(*(uint32_t*)&r0, *(uint32_t*)&r1);
        }
    }
}

// ===========================================================================
// GEMM body: fp16 in, 4-stage cp.async pipeline, fp16 or fp32 out.
// BM=128, BN=256, BK=32, 512 threads, warp tile 32x64.
// ===========================================================================
#define PADH 40
#define ROWB (PADH * 2)                 // 80 bytes per padded row
#define STG_B ((128 + 256) * ROWB)      // 30720 bytes per stage
#define NSTG 4
#define GEMM_SMEM (NSTG * STG_B)        // 122880

__device__ __forceinline__ void gemm_body(
    const __half* __restrict__ A, const __half* __restrict__ W,
    const float* __restrict__ bias, __half* __restrict__ C,
    float* __restrict__ Cf, int act, int m0, int n0, char* smc)
{
    const uint32_t sbase = (uint32_t)__cvta_generic_to_shared(smc);

    const int tid  = threadIdx.x;
    const int lane = tid & 31;
    const int wid  = tid >> 5;
    const int wm   = wid & 3;
    const int wn   = wid >> 2;
    const int g    = lane >> 2;
    const int tq   = lane & 3;

    float acc[2][8][4];
#pragma unroll
    for (int i = 0; i < 2; i++)
#pragma unroll
        for (int j = 0; j < 8; j++)
#pragma unroll
            for (int c = 0; c < 4; c++) acc[i][j][c] = 0.f;

    const int ar = tid >> 2, ac = tid & 3;
    const int br0 = tid >> 2, bc0 = tid & 3;
    const int br1 = (tid + 512) >> 2, bc1 = (tid + 512) & 3;

    const __half* Ag = A + (size_t)m0 * DD;
    const __half* Wg = W + (size_t)n0 * DD;

    uint32_t aoff[2], boff[4];
#pragma unroll
    for (int mi = 0; mi < 2; mi++)
        aoff[mi] = (wm * 32 + mi * 16 + (lane & 15)) * PADH + ((lane >> 4) << 3);
#pragma unroll
    for (int pi = 0; pi < 4; pi++)
        boff[pi] = (128 + wn * 64 + pi * 16 + (lane & 7) + ((lane & 16) >> 1)) * PADH + (lane & 8);

    // prologue: issue ktiles 0,1,2
#pragma unroll
    for (int p = 0; p < 3; p++) {
        const uint32_t st = sbase + p * STG_B;
        cpasync16(st + ar * ROWB + ac * 16, Ag + (size_t)ar * DD + p * 32 + ac * 8);
        cpasync16(st + 128 * ROWB + br0 * ROWB + bc0 * 16, Wg + (size_t)br0 * DD + p * 32 + bc0 * 8);
        cpasync16(st + 128 * ROWB + br1 * ROWB + bc1 * 16, Wg + (size_t)br1 * DD + p * 32 + bc1 * 8);
        CP_COMMIT();
    }

    for (int kt = 0; kt < 16; kt++) {
        CP_WAIT2();
        __syncthreads();

        const uint32_t stg = sbase + (kt & (NSTG - 1)) * STG_B;
#pragma unroll
        for (int ks = 0; ks < 32; ks += 16) {
            uint32_t af[2][4], bf[8][2];
#pragma unroll
            for (int mi = 0; mi < 2; mi++)
                ldsm4(af[mi], stg + (aoff[mi] + ks) * 2);
#pragma unroll
            for (int pi = 0; pi < 4; pi++) {
                uint32_t r[4];
                ldsm4(r, stg + (boff[pi] + ks) * 2);
                bf[2 * pi][0] = r[0]; bf[2 * pi][1] = r[1];
                bf[2 * pi + 1][0] = r[2]; bf[2 * pi + 1][1] = r[3];
            }
#pragma unroll
            for (int mi = 0; mi < 2; mi++)
#pragma unroll
                for (int ni = 0; ni < 8; ni++)
                    mma16816(acc[mi][ni], af[mi], bf[ni]);
        }

        if (kt + 3 < 16) {
            const uint32_t st = sbase + ((kt + 3) & (NSTG - 1)) * STG_B;
            const int kk = (kt + 3) * 32;
            cpasync16(st + ar * ROWB + ac * 16, Ag + (size_t)ar * DD + kk + ac * 8);
            cpasync16(st + 128 * ROWB + br0 * ROWB + bc0 * 16, Wg + (size_t)br0 * DD + kk + bc0 * 8);
            cpasync16(st + 128 * ROWB + br1 * ROWB + bc1 * 16, Wg + (size_t)br1 * DD + kk + bc1 * 8);
        }
        CP_COMMIT();
    }

    const bool f32out = (Cf != nullptr);
#pragma unroll
    for (int mi = 0; mi < 2; mi++) {
        const int row = m0 + wm * 32 + mi * 16 + g;
#pragma unroll
        for (int ni = 0; ni < 8; ni++) {
            const int col = n0 + wn * 64 + ni * 8 + tq * 2;
            const float b0 = bias[col], b1 = bias[col + 1];
            float v0 = acc[mi][ni][0] + b0;
            float v1 = acc[mi][ni][1] + b1;
            float v2 = acc[mi][ni][2] + b0;
            float v3 = acc[mi][ni][3] + b1;
            if (act) {
                v0 = (v0 > 0.f) ? (v0 + 1.f) : __expf(v0);
                v1 = (v1 > 0.f) ? (v1 + 1.f) : __expf(v1);
                v2 = (v2 > 0.f) ? (v2 + 1.f) : __expf(v2);
                v3 = (v3 > 0.f) ? (v3 + 1.f) : __expf(v3);
            }
            if (f32out) {
                *(float2*)(Cf + (size_t)row * DD + col)       = make_float2(v0, v1);
                *(float2*)(Cf + (size_t)(row + 8) * DD + col) = make_float2(v2, v3);
            } else {
                *(__half2*)(C + (size_t)row * DD + col)       = __floats2half2_rn(v0, v1);
                *(__half2*)(C + (size_t)(row + 8) * DD + col) = __floats2half2_rn(v2, v3);
            }
        }
    }
}

// gemm_cp_kernel: up to 2 fused fp16-out problems (z) OR single fp32-out (Cf)
__global__ void __launch_bounds__(512, 1)
gemm_cp_kernel(const __half* __restrict__ A0, const __half* __restrict__ W0,
               const float* __restrict__ b0p, __half* __restrict__ C0, int act0,
               const __half* __restrict__ A1, const __half* __restrict__ W1,
               const float* __restrict__ b1p, __half* __restrict__ C1, int act1,
               float* __restrict__ Cf)
{
    extern __shared__ char smc[];
    const int z = blockIdx.z;
    const __half* A = (z == 0) ? A0 : A1;
    const __half* W = (z == 0) ? W0 : W1;
    const float* bias = (z == 0) ? b0p : b1p;
    __half* C = (z == 0) ? C0 : C1;
    const int act = (z == 0) ? act0 : act1;
    gemm_body(A, W, bias, C, (z == 0) ? Cf : nullptr, act,
              blockIdx.y * 128, blockIdx.x * 256, smc);
}

// ===========================================================================
// KV reduce body (512 threads, 16 warps, warp tile 16x16):
// per (bh, chunk): kv[m][d] = sum_s V[s][m]*K[s][d] over 256 rows; z partial.
// ===========================================================================
#define FPK 72
#define KV_BYTES (2 * 256 * FPK * 2)    // 73728
#define ZRED_OFF KV_BYTES               // float[8][64] after tiles

__device__ __forceinline__ void kv_body(
    const __half* __restrict__ Kmat, const __half* __restrict__ Vmat,
    int bh, int chunk, char* smem)
{
    __half* Ks = (__half*)smem;              // [256][FPK]
    __half* Vs = Ks + 256 * FPK;
    float (*zred)[DHD] = (float(*)[DHD])(smem + ZRED_OFF);
    const uint32_t sbase = (uint32_t)__cvta_generic_to_shared(smem);

    const int b = bh / HH, h = bh % HH;
    const int s0g = chunk * 256;

    const __half* Kbase = Kmat + (size_t)b * SS * DD + (size_t)s0g * DD + h * DHD;
    const __half* Vbase = Vmat + (size_t)b * SS * DD + (size_t)s0g * DD + h * DHD;

    const int tid = threadIdx.x;
    const int lane = tid & 31;
    const int wid = tid >> 5;
    const int wm = wid & 3;          // 4 m-warps * 16
    const int wn = wid >> 2;         // 4 d-warps * 16
    const int g = lane >> 2;
    const int tq = lane & 3;

#pragma unroll
    for (int j = 0; j < 4; j++) {
        const int id = tid + 512 * j;
        const int row = id >> 3;
        const int c8 = (id & 7) * 8;
        *(uint4*)(Ks + row * FPK + c8) = *(const uint4*)(Kbase + (size_t)row * DD + c8);
        *(uint4*)(Vs + row * FPK + c8) = *(const uint4*)(Vbase + (size_t)row * DD + c8);
    }
    __syncthreads();

    const uint32_t aoff = (uint32_t)(256 * FPK)
                        + ((lane & 7) + ((lane & 16) >> 1)) * FPK
                        + (wm * 16 + (lane & 8));
    const uint32_t boff = ((lane & 7) + (lane & 8)) * FPK
                        + (wn * 16 + ((lane & 16) >> 1));

    float acc[2][4];
#pragma unroll
    for (int j = 0; j < 2; j++)
#pragma unroll
        for (int c = 0; c < 4; c++) acc[j][c] = 0.f;

#pragma unroll 4
    for (int s = 0; s < 256; s += 16) {
        uint32_t af[4], bt[4];
        ldsm4t(af, sbase + (aoff + s * FPK) * 2);
        ldsm4t(bt, sbase + (boff + s * FPK) * 2);
        uint32_t bf0[2] = {bt[0], bt[1]};
        uint32_t bf1[2] = {bt[2], bt[3]};
        mma16816(acc[0], af, bf0);
        mma16816(acc[1], af, bf1);
    }

    {
        const int dcol = tid & 63;
        const int part = tid >> 6;       // 0..7 * 32 rows
        float zs = 0.f;
#pragma unroll 8
        for (int i = 0; i < 32; i++)
            zs += __half2float(Ks[(part * 32 + i) * FPK + dcol]);
        zred[part][dcol] = zs;
    }
    __syncthreads();
    if (tid < DHD) {
        float s = 0.f;
#pragma unroll
        for (int p = 0; p < 8; p++) s += zred[p][tid];
        g_z_part[((size_t)chunk * (BB * HH) + bh) * DHD + tid] = s;
    }

    float* kvp = g_kv_part + ((size_t)chunk * (BB * HH) + bh) * DHD * DHD;
    const int m = wm * 16 + g;
#pragma unroll
    for (int ni = 0; ni < 2; ni++) {
        const int d = wn * 16 + ni * 8 + tq * 2;
        *(float2*)&kvp[m * DHD + d]       = make_float2(acc[ni][0], acc[ni][1]);
        *(float2*)&kvp[(m + 8) * DHD + d] = make_float2(acc[ni][2], acc[ni][3]);
    }
}

// ===========================================================================
// Phase 2: Q-GEMM (512 blocks) + kv_reduce (1024 blocks), interleaved 1:2
// ===========================================================================
__global__ void __launch_bounds__(512, 1)
phase2_kernel(const __half* __restrict__ Aq, const __half* __restrict__ Wqh,
              const float* __restrict__ bq, __half* __restrict__ Cq,
              const __half* __restrict__ Kmat, const __half* __restrict__ Vmat)
{
    extern __shared__ char smc[];
    const int blk = blockIdx.x;
    if (blk % 3 == 0) {
        const int gi = blk / 3;           // 0..511
        gemm_body(Aq, Wqh, bq, Cq, nullptr, 1, (gi >> 1) * 128, (gi & 1) * 256, smc);
    } else {
        const int ki = blk - blk / 3 - 1; // 0..1023
        kv_body(Kmat, Vmat, ki & 31, ki >> 5, smc);
    }
}

// ===========================================================================
// Finalize
// ===========================================================================
__global__ void __launch_bounds__(256)
kv_finalize_kernel(float* __restrict__ dout, int write_out)
{
    const int idx = blockIdx.x * blockDim.x + threadIdx.x;
    if (idx < NKV) {
        float s = 0.f;
#pragma unroll
        for (int c = 0; c < KVC; c++) s += g_kv_part[(size_t)c * NKV + idx];
        const int bh = idx >> 12;
        const int rem = idx & 4095;     // m*64 + d
        const int m = rem >> 6;
        const int d = rem & 63;
        g_kvT[bh * 4096 + rem] = __float2half(s);
        if (write_out) dout[OFF_KV + bh * 4096 + d * 64 + m] = s;
    } else if (idx < NKV + NZ) {
        const int id2 = idx - NKV;
        float s = 0.f;
#pragma unroll
        for (int c = 0; c < KVC; c++) s += g_z_part[(size_t)c * NZ + id2];
        g_z[id2] = s;
        if (write_out) dout[OFF_Z + id2] = s;
    }
}

// ===========================================================================
// Attention apply
// ===========================================================================
#define FP 72

__global__ void __launch_bounds__(256, 2)
attn_apply_kernel(const __half* __restrict__ Q)
{
    __shared__ __half Qh[128 * FP];
    __shared__ __half KVh[64 * FP];
    __shared__ float zf[DHD];
    __shared__ float invden[128];
    const uint32_t sbase = (uint32_t)__cvta_generic_to_shared(Qh);
    const uint32_t kvbase = (uint32_t)__cvta_generic_to_shared(KVh);

    const int bh = blockIdx.x;
    const int chunk = blockIdx.y;
    const int b = bh / HH, h = bh % HH;
    const int m0 = chunk * 128;

    const int tid = threadIdx.x;
    const int lane = tid & 31;
    const int wid = tid >> 5;
    const int g = lane >> 2;
    const int tq = lane & 3;

    const __half* Qbase = Q + (size_t)b * SS * DD + (size_t)m0 * DD + h * DHD;

#pragma unroll
    for (int j = 0; j < 4; j++) {
        const int id = tid + 256 * j;
        const int row = id >> 3;
        const int c8 = (id & 7) * 8;
        *(uint4*)(Qh + row * FP + c8) = *(const uint4*)(Qbase + (size_t)row * DD + c8);
    }
    {
        const uint32_t* src = (const uint32_t*)(g_kvT + (size_t)bh * 4096);
        uint32_t* dst = (uint32_t*)KVh;
#pragma unroll
        for (int j = 0; j < 8; j++) {
            const int w = tid + 256 * j;
            const int m = w >> 5;
            const int dw = w & 31;
            dst[m * (FP / 2) + dw] = src[w];
        }
    }
    if (tid < DHD) zf[tid] = g_z[bh * DHD + tid];
    __syncthreads();

    {
        const int r = tid >> 1;
        const int o = tid & 1;
        float s = 0.f;
        const __half2* qrow = (const __half2*)(Qh + r * FP) + o * 16;
#pragma unroll
        for (int i = 0; i < 16; i++) {
            float2 qf = __half22float2(qrow[i]);
            const int d = o * 32 + i * 2;
            s = fmaf(qf.x, zf[d], s);
            s = fmaf(qf.y, zf[d + 1], s);
        }
        s += __shfl_xor_sync(0xffffffffu, s, 1);
        if (o == 0) invden[r] = 1.0f / (s + EPSF);
    }
    __syncthreads();

    const uint32_t qoff = (wid * 16 + (lane & 15)) * FP + ((lane >> 4) << 3);
    uint32_t kvoff[4];
#pragma unroll
    for (int pi = 0; pi < 4; pi++)
        kvoff[pi] = (pi * 16 + (lane & 7) + ((lane & 16) >> 1)) * FP + (lane & 8);

    float aacc[8][4];
#pragma unroll
    for (int j = 0; j < 8; j++)
#pragma unroll
        for (int c = 0; c < 4; c++) aacc[j][c] = 0.f;

#pragma unroll
    for (int kt = 0; kt < 4; kt++) {
        uint32_t af[4], bf[8][2];
        ldsm4(af, sbase + (qoff + kt * 16) * 2);
#pragma unroll
        for (int pi = 0; pi < 4; pi++) {
            uint32_t r[4];
            ldsm4(r, kvbase + (kvoff[pi] + kt * 16) * 2);
            bf[2 * pi][0] = r[0]; bf[2 * pi][1] = r[1];
            bf[2 * pi + 1][0] = r[2]; bf[2 * pi + 1][1] = r[3];
        }
#pragma unroll
        for (int ni = 0; ni < 8; ni++)
            mma16816(aacc[ni], af, bf[ni]);
    }

    __half* Obase = g_att + (size_t)b * SS * DD + (size_t)m0 * DD + h * DHD;
    const int r = wid * 16 + g;
    const float i0 = invden[r];
    const float i1 = invden[r + 8];
#pragma unroll
    for (int ni = 0; ni < 8; ni++) {
        const int col = ni * 8 + tq * 2;
        *(__half2*)(Obase + (size_t)r * DD + col) =
            __floats2half2_rn(aacc[ni][0] * i0, aacc[ni][1] * i0);
        *(__half2*)(Obase + (size_t)(r + 8) * DD + col) =
            __floats2half2_rn(aacc[ni][2] * i1, aacc[ni][3] * i1);
    }
}

// ===========================================================================
// Launch
// ===========================================================================
extern "C" void kernel_launch(void* const* d_in, const int* in_sizes, int n_in,
                              void* d_out, int out_size)
{
    const float* q  = (const float*)d_in[0];
    const float* k  = (const float*)d_in[1];
    const float* v  = (const float*)d_in[2];
    const float* Wq = (const float*)d_in[3];
    const float* bq = (const float*)d_in[4];
    const float* Wk = (const float*)d_in[5];
    const float* bk = (const float*)d_in[6];
    const float* Wv = (const float*)d_in[7];
    const float* bv = (const float*)d_in[8];
    const float* Wo = (const float*)d_in[9];
    const float* bo = (const float*)d_in[10];
    float* out = (float*)d_out;

    __half *gqh, *gkh, *gvh, *gWh, *gQ, *gK, *gV, *gA;
    cudaGetSymbolAddress((void**)&gqh, g_qh);
    cudaGetSymbolAddress((void**)&gkh, g_kh);
    cudaGetSymbolAddress((void**)&gvh, g_vh);
    cudaGetSymbolAddress((void**)&gWh, g_Wh4);
    cudaGetSymbolAddress((void**)&gQ, g_Q);
    cudaGetSymbolAddress((void**)&gK, g_K);
    cudaGetSymbolAddress((void**)&gV, g_V);
    cudaGetSymbolAddress((void**)&gA, g_att);

    const int write_extra = ((size_t)out_size >= OFF_Z + NZ) ? 1 : 0;

    cudaFuncSetAttribute(gemm_cp_kernel,
                         cudaFuncAttributeMaxDynamicSharedMemorySize, GEMM_SMEM);
    cudaFuncSetAttribute(phase2_kernel,
                         cudaFuncAttributeMaxDynamicSharedMemorySize, GEMM_SMEM);

    cvt_inputs_kernel<<<2048, 256>>>(q, k, v);
    cvt_weights_kernel<<<(DD * DD / 4 + 255) / 256, 256>>>(Wq, Wk, Wv, Wo);

    // K and V GEMMs fused into one launch
    dim3 gemm2_grid(DD / 256, MR / 128, 2);
    gemm_cp_kernel<<<gemm2_grid, 512, GEMM_SMEM>>>(
        gkh, gWh + (size_t)1 * DD * DD, bk, gK, 1,
        gvh, gWh + (size_t)2 * DD * DD, bv, gV, 0,
        nullptr);

    // Phase 2: Q-GEMM overlapped with kv_reduce
    phase2_kernel<<<1536, 512, GEMM_SMEM>>>(
        gqh, gWh + (size_t)0 * DD * DD, bq, gQ, gK, gV);

    const int fin_total = NKV + NZ;
    kv_finalize_kernel<<<(fin_total + 255) / 256, 256>>>(out, write_extra);

    dim3 att_grid(BB * HH, SS / 128);
    attn_apply_kernel<<<att_grid, 256>>>(gQ);

    // Output GEMM: att @ Wo^T + bo -> fp32 out
    dim3 gemm1_grid(DD / 256, MR / 128, 1);
    gemm_cp_kernel<<<gemm1_grid, 512, GEMM_SMEM>>>(
        gA, gWh + (size_t)3 * DD * DD, bo, nullptr, 0,
        nullptr, nullptr, nullptr, nullptr, 0,
        out);
}